// round 8
// baseline (speedup 1.0000x reference)
#include <cuda_runtime.h>
#include <cuda_bf16.h>
#include <mma.h>
#include <cstdint>

using namespace nvcuda;

// Problem constants
#define BB 32
#define T_IN 1024
#define HH 384
#define T_OUTC 8192
#define KW 11
#define KK_TOT (KW*HH)          // 4224 = im2col K

// ---------------- scratch (static device globals; no allocations) -----------
__device__ float g_m1[BB*T_IN*HH];
__device__ float g_m2[BB*T_IN*HH];
__device__ __nv_bfloat16 g_wh1[HH*KK_TOT];   // hi part, [o][k*384+i] (B col-major)
__device__ __nv_bfloat16 g_wl1[HH*KK_TOT];   // lo part
__device__ __nv_bfloat16 g_wh2[HH*KK_TOT];
__device__ __nv_bfloat16 g_wl2[HH*KK_TOT];
__device__ float g_cum[BB*T_IN];

// ---------------- smem layout for conv_wmma ---------------------------------
#define LDS_ST 388                          // fp32 store row stride (×4B, 16B mult)
#define SM_ST  0                            // 128 x 388 fp32 = 198656 B
#define SM_AH  198656                       // 128 x 64 bf16 = 16384 B
#define SM_AL  (SM_AH + 16384)              // 215040
#define SM_TOTAL (SM_AL + 16384)            // 231424 B (< 227 KB limit)

// ---------------- weight split prep: w[o][i][k] -> (hi,lo)[o][k*384+i] ------
__global__ void wprep(const float* __restrict__ w, __nv_bfloat16* __restrict__ bh,
                      __nv_bfloat16* __restrict__ bl) {
    int idx = blockIdx.x * blockDim.x + threadIdx.x;
    if (idx >= HH * KK_TOT) return;
    int o  = idx / KK_TOT;
    int kk = idx % KK_TOT;
    int k  = kk / HH;
    int i  = kk % HH;
    float v = w[o * KK_TOT + i * KW + k];
    __nv_bfloat16 h = __float2bfloat16(v);
    bh[idx] = h;
    bl[idx] = __float2bfloat16(v - __bfloat162float(h));
}

// ---------------- conv1d as split-bf16 WMMA GEMM + bias + LN + ReLU ---------
// grid 256 (M-tiles of 128 rows, batch-aligned), block 512 (16 warps), 1 CTA/SM.
// Warp (slice = wid>>1) owns rows [16*slice,16*slice+16); nq = wid&1 picks a
// 96-col quarter inside the current 192-col N-half pass.
__global__ void __launch_bounds__(512, 1)
conv_wmma(const float* __restrict__ in, const __nv_bfloat16* __restrict__ wh,
          const __nv_bfloat16* __restrict__ wl, const float* __restrict__ cb,
          const float* __restrict__ lg, const float* __restrict__ lb,
          float* __restrict__ out) {
    extern __shared__ char smem[];
    float* sst = (float*)(smem + SM_ST);
    __nv_bfloat16* Ah = (__nv_bfloat16*)(smem + SM_AH);
    __nv_bfloat16* Al = (__nv_bfloat16*)(smem + SM_AL);

    const int tid   = threadIdx.x;
    const int wid   = tid >> 5;
    const int slice = wid >> 1;
    const int nq    = wid & 1;
    const int mt    = blockIdx.x;
    const int b     = mt >> 3;
    const int tt0   = (mt & 7) * 128;

    for (int nh = 0; nh < 2; nh++) {
        const int nc0 = nh * 192 + nq * 96;

        wmma::fragment<wmma::accumulator, 16, 16, 16, float> acc[6];
        #pragma unroll
        for (int f = 0; f < 6; f++) wmma::fill_fragment(acc[f], 0.0f);

        for (int c = 0; c < 66; c++) {
            const int k  = c / 6;
            const int i0 = (c - k * 6) * 64;
            __syncthreads();   // all warps done loading previous A chunk
            // ---- A fill: 128 rows x 64 cols fp32 -> (hi,lo) bf16, row-major ld=64
            #pragma unroll
            for (int it = 0; it < 8; it++) {
                int idx = tid + it * 512;          // 4096 float2 slots
                int row = idx >> 5, j2 = idx & 31;
                int tsrc = tt0 + row + k - 5;
                float v0 = 0.f, v1 = 0.f;
                if (tsrc >= 0 && tsrc < T_IN) {
                    const float2 p = *(const float2*)(in + ((size_t)(b * T_IN + tsrc)) * HH + i0 + 2 * j2);
                    v0 = p.x; v1 = p.y;
                }
                __nv_bfloat16 h0 = __float2bfloat16(v0), h1 = __float2bfloat16(v1);
                __nv_bfloat16 l0 = __float2bfloat16(v0 - __bfloat162float(h0));
                __nv_bfloat16 l1 = __float2bfloat16(v1 - __bfloat162float(h1));
                __nv_bfloat162 hh; hh.x = h0; hh.y = h1;
                __nv_bfloat162 ll; ll.x = l0; ll.y = l1;
                *(__nv_bfloat162*)(Ah + row * 64 + 2 * j2) = hh;
                *(__nv_bfloat162*)(Al + row * 64 + 2 * j2) = ll;
            }
            __syncthreads();

            const int kk0 = k * HH + i0;
            #pragma unroll
            for (int ks = 0; ks < 4; ks++) {
                wmma::fragment<wmma::matrix_a, 16, 16, 16, __nv_bfloat16, wmma::row_major> a_hi, a_lo;
                wmma::load_matrix_sync(a_hi, Ah + slice * 16 * 64 + ks * 16, 64);
                wmma::load_matrix_sync(a_lo, Al + slice * 16 * 64 + ks * 16, 64);
                #pragma unroll
                for (int nf = 0; nf < 6; nf++) {
                    const size_t boff = (size_t)(nc0 + nf * 16) * KK_TOT + kk0 + ks * 16;
                    wmma::fragment<wmma::matrix_b, 16, 16, 16, __nv_bfloat16, wmma::col_major> b_hi, b_lo;
                    wmma::load_matrix_sync(b_hi, wh + boff, KK_TOT);
                    wmma::load_matrix_sync(b_lo, wl + boff, KK_TOT);
                    wmma::mma_sync(acc[nf], a_hi, b_hi, acc[nf]);
                    wmma::mma_sync(acc[nf], a_hi, b_lo, acc[nf]);
                    wmma::mma_sync(acc[nf], a_lo, b_hi, acc[nf]);
                }
            }
        }
        // store this pass's 192 columns (disjoint from A smem region)
        #pragma unroll
        for (int nf = 0; nf < 6; nf++)
            wmma::store_matrix_sync(sst + (size_t)slice * 16 * LDS_ST + nc0 + nf * 16,
                                    acc[nf], LDS_ST, wmma::mem_row_major);
    }
    __syncthreads();

    // ---- LayerNorm: 4 threads per row (quarters), quad shuffle reduce ----
    {
        const int r = tid >> 2, q = tid & 3;
        float s1 = 0.f, s2 = 0.f;
        #pragma unroll 4
        for (int j = 0; j < 96; j++) {
            int o = q * 96 + j;
            float v = sst[(size_t)r * LDS_ST + o] + __ldg(&cb[o]);
            s1 += v; s2 += v * v;
        }
        s1 += __shfl_xor_sync(0xffffffffu, s1, 1);
        s2 += __shfl_xor_sync(0xffffffffu, s2, 1);
        s1 += __shfl_xor_sync(0xffffffffu, s1, 2);
        s2 += __shfl_xor_sync(0xffffffffu, s2, 2);
        if (q == 0) {
            float mu  = s1 * (1.0f / HH);
            float var = s2 * (1.0f / HH) - mu * mu;
            sst[(size_t)r * LDS_ST + 384] = mu;
            sst[(size_t)r * LDS_ST + 385] = rsqrtf(var + 1e-5f);
        }
    }
    __syncthreads();

    // ---- apply + ReLU + coalesced store: 128 rows x 96 float4 ----
    for (int it = 0; it < 24; it++) {
        int idx = tid + it * 512;
        int row = idx / 96, c4 = idx - row * 96;
        float mu = sst[(size_t)row * LDS_ST + 384];
        float rs = sst[(size_t)row * LDS_ST + 385];
        float4 o4;
        #pragma unroll
        for (int e = 0; e < 4; e++) {
            int o = c4 * 4 + e;
            float v = sst[(size_t)row * LDS_ST + o] + __ldg(&cb[o]);
            float y = (v - mu) * rs * __ldg(&lg[o]) + __ldg(&lb[o]);
            (&o4.x)[e] = fmaxf(y, 0.0f);
        }
        *(float4*)(out + ((size_t)mt * 128 + row) * HH + c4 * 4) = o4;
    }
}

// ---------------- linear head + token mask ----------------------------------
__global__ void lin_mask(const float* __restrict__ m, const float* __restrict__ lw,
                         const float* __restrict__ lbias, const int* __restrict__ tok,
                         float* __restrict__ pred) {
    int row  = blockIdx.x * 4 + (threadIdx.x >> 5);
    int lane = threadIdx.x & 31;
    const float* mr = m + (size_t)row * HH;
    float s = 0.f;
    #pragma unroll
    for (int j = 0; j < 12; j++) {
        int o = lane + 32 * j;
        s += mr[o] * lw[o];
    }
    #pragma unroll
    for (int off = 16; off > 0; off >>= 1)
        s += __shfl_xor_sync(0xffffffffu, s, off);
    if (lane == 0) {
        int b = row >> 10;
        int t = row & 1023;
        float v = s + lbias[0];
        pred[row] = (t < tok[b]) ? v : 0.0f;
    }
}

// ---------------- cumsum matching XLA ReduceWindowRewriter(base=16) ----------
__global__ void cum_kernel(const float* __restrict__ dur, const int* __restrict__ gt,
                           float* __restrict__ cum) {
    __shared__ float T[64];
    __shared__ float U[4];
    __shared__ float OS[64];
    const int b = blockIdx.x;
    const int t = threadIdx.x;   // 64 threads
    const float* d = dur + (size_t)b * T_IN + t * 16;

    float p[16];
    float s = 0.0f;
    #pragma unroll 1
    for (int j = 0; j < 16; j++) { s = s + d[j]; p[j] = s; }
    T[t] = s;
    __syncthreads();

    const int c = t >> 4, m = t & 15;
    float s2 = 0.0f;
    #pragma unroll 1
    for (int k = 0; k <= m; k++) s2 = s2 + T[c * 16 + k];
    if (m == 15) U[c] = s2;
    __syncthreads();

    float ex2 = 0.0f;
    #pragma unroll 1
    for (int k = 0; k < c; k++) ex2 = ex2 + U[k];
    float os = (c > 0) ? (s2 + ex2) : s2;
    OS[t] = os;
    __syncthreads();

    const float pre = (t > 0) ? OS[t - 1] : 0.0f;
    const float g   = (float)gt[b];
    float* co = cum + (size_t)b * T_IN + t * 16;
    #pragma unroll
    for (int j = 0; j < 16; j++) {
        float v = (t > 0) ? (p[j] + pre) : p[j];
        co[j] = fminf(v, g);
    }
}

// ---------------- length regulation gather -----------------------------------
__global__ void gather_kernel(const float* __restrict__ x, const float* __restrict__ cum,
                              const int* __restrict__ gt, float* __restrict__ out) {
    int w    = blockIdx.x * 8 + (threadIdx.x >> 5);
    int lane = threadIdx.x & 31;
    int b = w >> 13;
    int f = w & (T_OUTC - 1);
    float4* orow = (float4*)(out + (size_t)w * HH);
    if (f >= gt[b]) {
        float4 z = make_float4(0.f, 0.f, 0.f, 0.f);
        #pragma unroll
        for (int j = 0; j < 3; j++) orow[lane + 32 * j] = z;
        return;
    }
    const float* c = cum + (size_t)b * T_IN;
    float ff = (float)f;
    int lo = 0, hi = T_IN;
    while (lo < hi) {
        int mid = (lo + hi) >> 1;
        if (c[mid] <= ff) lo = mid + 1; else hi = mid;
    }
    int idx = lo < (T_IN - 1) ? lo : (T_IN - 1);
    const float4* xrow = (const float4*)(x + ((size_t)b * T_IN + idx) * HH);
    #pragma unroll
    for (int j = 0; j < 3; j++) orow[lane + 32 * j] = xrow[lane + 32 * j];
}

// ---------------- launch ------------------------------------------------------
extern "C" void kernel_launch(void* const* d_in, const int* in_sizes, int n_in,
                              void* d_out, int out_size) {
    const float* x   = (const float*)d_in[0];
    const int*   tok = (const int*)d_in[1];
    const float* dur = (const float*)d_in[2];
    const int*   gt  = (const int*)d_in[3];
    int base = (in_sizes[4] == HH * HH * KW) ? 4 : 5;
    const float* c1w = (const float*)d_in[base + 0];
    const float* c1b = (const float*)d_in[base + 1];
    const float* l1g = (const float*)d_in[base + 2];
    const float* l1b = (const float*)d_in[base + 3];
    const float* c2w = (const float*)d_in[base + 4];
    const float* c2b = (const float*)d_in[base + 5];
    const float* l2g = (const float*)d_in[base + 6];
    const float* l2b = (const float*)d_in[base + 7];
    const float* lw  = (const float*)d_in[base + 8];
    const float* lbv = (const float*)d_in[base + 9];

    float* out      = (float*)d_out;
    float* pred_out = out + (size_t)BB * T_OUTC * HH;

    float *m1, *m2, *cum;
    __nv_bfloat16 *wh1, *wl1, *wh2, *wl2;
    cudaGetSymbolAddress((void**)&m1,  g_m1);
    cudaGetSymbolAddress((void**)&m2,  g_m2);
    cudaGetSymbolAddress((void**)&wh1, g_wh1);
    cudaGetSymbolAddress((void**)&wl1, g_wl1);
    cudaGetSymbolAddress((void**)&wh2, g_wh2);
    cudaGetSymbolAddress((void**)&wl2, g_wl2);
    cudaGetSymbolAddress((void**)&cum, g_cum);

    cudaFuncSetAttribute(conv_wmma, cudaFuncAttributeMaxDynamicSharedMemorySize, SM_TOTAL);

    // weight split prep
    {
        int n = HH * KK_TOT;
        int gsz = (n + 255) / 256;
        wprep<<<gsz, 256>>>(c1w, wh1, wl1);
        wprep<<<gsz, 256>>>(c2w, wh2, wl2);
    }

    // length-regulation path (independent of predictor)
    cum_kernel<<<BB, 64>>>(dur, gt, cum);
    gather_kernel<<<(BB * T_OUTC) / 8, 256>>>(x, cum, gt, out);

    // duration predictor: two WMMA conv layers + linear head
    conv_wmma<<<256, 512, SM_TOTAL>>>(x,  wh1, wl1, c1b, l1g, l1b, m1);
    conv_wmma<<<256, 512, SM_TOTAL>>>(m1, wh2, wl2, c2b, l2g, l2b, m2);
    lin_mask<<<(BB * T_IN) / 4, 128>>>(m2, lw, lbv, tok, pred_out);
}